// round 15
// baseline (speedup 1.0000x reference)
#include <cuda_runtime.h>

#define N     512
#define B     32
#define NF4   (N / 4)
#define NT    128
#define NWP   4
#define ROOTW 0xFFFF

__device__ double g_batch_sums[B];

// thread owns cols [4*tid, 4*tid+4); one float4 per thread per row (coalesced)
#define LOADROW(dst, row)                                                    \
    do {                                                                     \
        float4 _t = C4[(size_t)(row) * NF4 + tid];                           \
        dst[0] = _t.x; dst[1] = _t.y; dst[2] = _t.z; dst[3] = _t.w;          \
    } while (0)

__global__ __launch_bounds__(NT, 1)
void lap_kernel(const float* __restrict__ D)
{
    const int b    = blockIdx.x;
    const int tid  = threadIdx.x;
    const int lane = tid & 31;
    const int wrp  = tid >> 5;
    const int jc0  = tid << 2;
    const float*  __restrict__ C  = D + (size_t)b * N * N;
    const float4* __restrict__ C4 = (const float4*)C;

    __shared__ float          u[N];
    __shared__ int            prow[N];
    __shared__ unsigned short way[N];
    __shared__ float          dpop[N];
    __shared__ short          aminS[N];
    __shared__ unsigned char  rowUsed[N];
    __shared__ short          flist[3 * N];
    __shared__ short          alist[N];
    __shared__ int            s_nfree, s_iold, s_na;
    __shared__ __align__(16) unsigned red1[2][NWP];
    __shared__ __align__(16) unsigned red2[2][NWP];
    __shared__ double         red_s[NWP];

    for (int k = tid; k < N; k += NT) { u[k] = 0.f; prow[k] = -1; rowUsed[k] = 0; }

    const float INF = __uint_as_float(0x7F800000u);

    // ================= column reduction: v[j] = min_i C[i][j] ==============
    float v[4]; short amin[4];
#pragma unroll
    for (int k = 0; k < 4; ++k) { v[k] = INF; amin[k] = 0; }

    float c[4], cS[4], cT[4];
    for (int r = 0; r < N; r += 2) {
        float4 t0 = C4[(size_t)r * NF4 + tid];
        float4 t1 = C4[(size_t)(r + 1) * NF4 + tid];
        float a0[4] = {t0.x, t0.y, t0.z, t0.w};
        float a1[4] = {t1.x, t1.y, t1.z, t1.w};
#pragma unroll
        for (int k = 0; k < 4; ++k)
            if (a0[k] < v[k]) { v[k] = a0[k]; amin[k] = (short)r; }
#pragma unroll
        for (int k = 0; k < 4; ++k)
            if (a1[k] < v[k]) { v[k] = a1[k]; amin[k] = (short)(r + 1); }
    }
#pragma unroll
    for (int k = 0; k < 4; ++k) aminS[jc0 + k] = amin[k];
    __syncthreads();

    // ================= greedy assignment + lists (tid 0) ===================
    if (tid == 0) {
        for (int j = 0; j < N; ++j) {
            int i = aminS[j];
            if (!rowUsed[i]) { rowUsed[i] = 1; prow[j] = i; }
        }
        int nf = 0, na = 0;
        for (int i = 0; i < N; ++i)
            if (!rowUsed[i]) flist[nf++] = (short)i;
        for (int j = 0; j < N; ++j)
            if (prow[j] >= 0) alist[na++] = (short)j;
        s_nfree = nf; s_na = na;
    }
    __syncthreads();

    int pp = 0;

    // ================= JV reduction transfer ================================
    {
        const int na = s_na;
        if (na > 0) LOADROW(c, prow[alist[0]]);
        for (int t = 0; t < na; ++t) {
            const int j1 = alist[t];
            float m = INF;
#pragma unroll
            for (int k = 0; k < 4; ++k) {
                float rc = c[k] - v[k];
                if (jc0 + k == j1) rc = INF;
                m = fminf(m, rc);
            }
            if (t + 1 < na) LOADROW(c, prow[alist[t + 1]]);

            unsigned mb = __reduce_min_sync(0xffffffffu, __float_as_uint(m));
            if (lane == 0) red1[pp][wrp] = mb;
            __syncthreads();
            const float mu = __uint_as_float(min(min(red1[pp][0], red1[pp][1]),
                                                 min(red1[pp][2], red1[pp][3])));
            if ((unsigned)(j1 - jc0) < 4u) v[j1 - jc0] -= mu;
            if (tid == 0) u[prow[j1]] = mu;
            pp ^= 1;
        }
        __syncthreads();
    }

    int head = 0, tail = s_nfree;
    const int lim = 2 * tail;
    int cnt = 0;

    // ================= augmenting row reduction (bounded JV ARR) ===========
    if (head < tail) LOADROW(c, flist[0]);
    while (head < tail && cnt < lim) {
        const int i = flist[head]; ++head; ++cnt;

        unsigned kk[4];
#pragma unroll
        for (int k = 0; k < 4; ++k) {
            float r0 = c[k] - v[k];
            kk[k] = (__float_as_uint(r0) & ~0x3FFu) | (unsigned)(jc0 + k);
        }
        unsigned m = min(min(kk[0], kk[1]), min(kk[2], kk[3]));
        m = __reduce_min_sync(0xffffffffu, m);
        if (lane == 0) red1[pp][wrp] = m;

        unsigned m2 = 0xFFFFFFFFu;
        __syncthreads();                                            // bar 1
        const unsigned g1 = min(min(red1[pp][0], red1[pp][1]),
                                min(red1[pp][2], red1[pp][3]));
        const int j1 = (int)(g1 & 0x3FFu);

#pragma unroll
        for (int k = 0; k < 4; ++k) m2 = min(m2, (kk[k] == g1) ? 0xFFFFFFFFu : kk[k]);
        m2 = __reduce_min_sync(0xffffffffu, m2);
        if (lane == 0) red2[pp][wrp] = m2;
        __syncthreads();                                            // bar 2
        const unsigned g2 = min(min(red2[pp][0], red2[pp][1]),
                                min(red2[pp][2], red2[pp][3]));
        const int j2 = (int)(g2 & 0x3FFu);
        const float u1 = __uint_as_float(g1 & ~0x3FFu);
        const float u2 = __uint_as_float(g2 & ~0x3FFu);

        int jsel = j1;
        if (u1 < u2) {
            if ((unsigned)(j1 - jc0) < 4u) v[j1 - jc0] -= (u2 - u1);
        } else if (prow[j1] >= 0) {
            jsel = j2;
        }
        if (tid == 0) {
            int iold = prow[jsel];
            prow[jsel] = i;
            u[i] = u2;
            if (iold >= 0) flist[tail] = (short)iold;
            s_iold = iold;
        }
        pp ^= 1;
        __syncthreads();                                            // bar 3
        if (s_iold >= 0) ++tail;
        if (head < tail && cnt < lim) LOADROW(c, flist[head]);
    }

    // ================= shortest augmenting paths ===========================
    if (head < tail) LOADROW(c, flist[head]);

    for (int idx = head; idx < tail; ++idx) {
        const int i = flist[idx];

        float          uinf[4];
        unsigned       key[4];
        unsigned short wreg[4];
        float          cv[4], cvS[4], cvT[4];    // reduced rows (c - v)
#pragma unroll
        for (int k = 0; k < 4; ++k) {
            uinf[k] = 0.f; key[k] = 0xFFFFFFFFu; wreg[k] = ROOTW;
            cv[k] = c[k] - v[k];                  // root row: hoisted once
        }

        float          base = -u[i];
        unsigned short j0s  = ROOTW;
        int   jpred1 = -1, jpred2 = -1;
        int   ipred1 = 0,  ipred2 = 0;
        float upred1 = 0.f, upred2 = 0.f;
        int   jfreeC;
        float dfinal;

        while (true) {
            // ---- relax my 4 columns (cv precomputed; 1 FADD per col) ----
#pragma unroll
            for (int k = 0; k < 4; ++k) {
                float cur   = fmaxf(cv[k] + base, uinf[k]);
                unsigned pc = (__float_as_uint(cur) & ~0x3FFu)
                              | (unsigned)(jc0 + k);
                if (pc < key[k]) { key[k] = pc; wreg[k] = j0s; }
            }
            unsigned m = min(min(key[0], key[1]), min(key[2], key[3]));
            m = __reduce_min_sync(0xffffffffu, m);
            if (lane == 0) red1[pp][wrp] = m;
            __syncthreads();                              // the ONLY bar per pop
            const uint4 q = *(const uint4*)&red1[pp][0];  // one LDS.128
            const unsigned gmin = min(min(q.x, q.y), min(q.z, q.w));
            const int   j1 = (int)(gmin & 0x3FFu);
            const float dl = __uint_as_float(gmin & ~0x3FFu);

            int   i1;
            float ui1;
            // ---- hit path: reduced row, dual, row index all in registers ----
            if (j1 == jpred1) {
                i1 = ipred1; ui1 = upred1;
#pragma unroll
                for (int k = 0; k < 4; ++k) cv[k] = cvS[k];
            } else if (j1 == jpred2) {
                i1 = ipred2; ui1 = upred2;
#pragma unroll
                for (int k = 0; k < 4; ++k) cv[k] = cvT[k];
            } else {
                i1 = prow[j1];                            // miss: LDS
                if (i1 < 0) {
#pragma unroll
                    for (int k = 0; k < 4; ++k)
                        if (key[k] == gmin) way[jc0 + k] = wreg[k];
                    jfreeC = j1; dfinal = dl; pp ^= 1; break;
                }
                LOADROW(c, i1);                           // LDG first ...
                ui1 = u[i1];                              // ... u LDS overlaps it
#pragma unroll
                for (int k = 0; k < 4; ++k) cv[k] = c[k] - v[k];
            }

            // ---- owner poisons its popped column; publishes dpop + way ----
#pragma unroll
            for (int k = 0; k < 4; ++k)
                if (key[k] == gmin) {
                    uinf[k] = INF;
                    key[k]  = 0x7F800000u | (unsigned)(jc0 + k);
                    dpop[jc0 + k] = dl;
                    way[jc0 + k]  = wreg[k];
                }

            // ---- predictions: 2 smallest losing warp minima, batched issue -
            {
                unsigned cA = 0xFFFFFFFFu, cB = 0xFFFFFFFFu, x;
                x = q.x; if (x != gmin) { if (x < cA) { cB = cA; cA = x; } else cB = min(cB, x); }
                x = q.y; if (x != gmin) { if (x < cA) { cB = cA; cA = x; } else cB = min(cB, x); }
                x = q.z; if (x != gmin) { if (x < cA) { cB = cA; cA = x; } else cB = min(cB, x); }
                x = q.w; if (x != gmin) { if (x < cA) { cB = cA; cA = x; } else cB = min(cB, x); }
                const int jpA = (int)(cA & 0x3FFu);
                const int jpB = (int)(cB & 0x3FFu);
                const bool okA = (cA < 0x7F800000u);
                const bool okB = (cB < 0x7F800000u) && (jpB != jpA);
                const int ipA = okA ? prow[jpA] : -1;
                const int ipB = okB ? prow[jpB] : -1;
                jpred1 = jpred2 = -1;
                if (ipA >= 0) LOADROW(cS, ipA);
                if (ipB >= 0) LOADROW(cT, ipB);
                if (ipA >= 0) { jpred1 = jpA; ipred1 = ipA; upred1 = u[ipA]; }
                if (ipB >= 0) { jpred2 = jpB; ipred2 = ipB; upred2 = u[ipB]; }
            }

            base = dl - ui1;
            j0s  = (unsigned short)j1;
            pp  ^= 1;

            // reduce speculated rows at loop bottom: LDG has a full pop of
            // slack to return; v is constant within this Dijkstra
            if (jpred1 >= 0) {
#pragma unroll
                for (int k = 0; k < 4; ++k) cvS[k] = cS[k] - v[k];
            }
            if (jpred2 >= 0) {
#pragma unroll
                for (int k = 0; k < 4; ++k) cvT[k] = cT[k] - v[k];
            }
        }

        __syncthreads();              // dpop/way visible; all past break

        // prefetch next root row before serial tail
        if (idx + 1 < tail) LOADROW(c, flist[idx + 1]);

        // ---- one-shot dual updates ----
#pragma unroll
        for (int k = 0; k < 4; ++k) {
            if (uinf[k] > 0.f) {                  // col was popped
                int   j   = jc0 + k;
                float adj = dfinal - dpop[j];
                v[k]       -= adj;
                u[prow[j]] += adj;                // distinct rows: race-free
            }
        }
        if (tid == 0) u[i] += dfinal;
        __syncthreads();

        // ---- augment along alternating path (serial, tid 0) ----
        if (tid == 0) {
            int j = jfreeC;
            while (true) {
                int jpth = way[j];
                if (jpth == ROOTW) { prow[j] = i; break; }
                prow[j] = prow[jpth];
                j = jpth;
            }
        }
        __syncthreads();
    }

    // ---- matched-cost sum (double, deterministic order) ----
    double s = 0.0;
#pragma unroll
    for (int k = 0; k < 4; ++k) {
        int j = jc0 + k;
        s += (double)__ldg(&C[(size_t)prow[j] * N + j]);
    }
#pragma unroll
    for (int off = 16; off; off >>= 1)
        s += __shfl_down_sync(0xffffffffu, s, off);
    if (lane == 0) red_s[wrp] = s;
    __syncthreads();
    if (tid == 0)
        g_batch_sums[b] = ((red_s[0] + red_s[1]) + (red_s[2] + red_s[3]));
}

__global__ void finalize_kernel(float* __restrict__ out)
{
    const int lane = threadIdx.x;
    double s = (lane < B) ? g_batch_sums[lane] : 0.0;
#pragma unroll
    for (int off = 16; off; off >>= 1)
        s += __shfl_down_sync(0xffffffffu, s, off);
    if (lane == 0) out[0] = (float)(s / (double)(B * N));
}

extern "C" void kernel_launch(void* const* d_in, const int* in_sizes, int n_in,
                              void* d_out, int out_size)
{
    const float* D = (const float*)d_in[0];
    lap_kernel<<<B, NT>>>(D);
    finalize_kernel<<<1, 32>>>((float*)d_out);
}

// round 16
// speedup vs baseline: 1.2157x; 1.2157x over previous
#include <cuda_runtime.h>

#define N     512
#define B     32
#define NF4   (N / 4)
#define NT    128
#define NWP   4
#define ROOTW 0xFFFF

__device__ double g_batch_sums[B];

// thread owns cols [4*tid, 4*tid+4); one float4 per thread per row (coalesced)
#define LOADROW(dst, row)                                                    \
    do {                                                                     \
        float4 _t = C4[(size_t)(row) * NF4 + tid];                           \
        dst[0] = _t.x; dst[1] = _t.y; dst[2] = _t.z; dst[3] = _t.w;          \
    } while (0)

__global__ __launch_bounds__(NT, 1)
void lap_kernel(const float* __restrict__ D)
{
    const int b    = blockIdx.x;
    const int tid  = threadIdx.x;
    const int lane = tid & 31;
    const int wrp  = tid >> 5;
    const int jc0  = tid << 2;
    const float*  __restrict__ C  = D + (size_t)b * N * N;
    const float4* __restrict__ C4 = (const float4*)C;

    __shared__ float          u[N];
    __shared__ int            prow[N];
    __shared__ unsigned short way[N];
    __shared__ float          dpop[N];
    __shared__ short          aminS[N];
    __shared__ unsigned char  rowUsed[N];
    __shared__ short          flist[3 * N];
    __shared__ short          alist[N];
    __shared__ int            s_nfree, s_iold, s_na;
    __shared__ __align__(16) unsigned red1[2][NWP];
    __shared__ __align__(16) unsigned red2[2][NWP];
    __shared__ double         red_s[NWP];

    for (int k = tid; k < N; k += NT) { u[k] = 0.f; prow[k] = -1; rowUsed[k] = 0; }

    const float INF = __uint_as_float(0x7F800000u);

    // ================= column reduction: v[j] = min_i C[i][j] ==============
    float v[4]; short amin[4];
#pragma unroll
    for (int k = 0; k < 4; ++k) { v[k] = INF; amin[k] = 0; }

    float c[4], cS[4], cT[4];
    for (int r = 0; r < N; r += 2) {
        float4 t0 = C4[(size_t)r * NF4 + tid];
        float4 t1 = C4[(size_t)(r + 1) * NF4 + tid];
        float a0[4] = {t0.x, t0.y, t0.z, t0.w};
        float a1[4] = {t1.x, t1.y, t1.z, t1.w};
#pragma unroll
        for (int k = 0; k < 4; ++k)
            if (a0[k] < v[k]) { v[k] = a0[k]; amin[k] = (short)r; }
#pragma unroll
        for (int k = 0; k < 4; ++k)
            if (a1[k] < v[k]) { v[k] = a1[k]; amin[k] = (short)(r + 1); }
    }
#pragma unroll
    for (int k = 0; k < 4; ++k) aminS[jc0 + k] = amin[k];
    __syncthreads();

    // ================= greedy assignment + lists (tid 0) ===================
    if (tid == 0) {
        for (int j = 0; j < N; ++j) {
            int i = aminS[j];
            if (!rowUsed[i]) { rowUsed[i] = 1; prow[j] = i; }
        }
        int nf = 0, na = 0;
        for (int i = 0; i < N; ++i)
            if (!rowUsed[i]) flist[nf++] = (short)i;
        for (int j = 0; j < N; ++j)
            if (prow[j] >= 0) alist[na++] = (short)j;
        s_nfree = nf; s_na = na;
    }
    __syncthreads();

    int pp = 0;

    // ================= JV reduction transfer ================================
    {
        const int na = s_na;
        if (na > 0) LOADROW(c, prow[alist[0]]);
        for (int t = 0; t < na; ++t) {
            const int j1 = alist[t];
            float m = INF;
#pragma unroll
            for (int k = 0; k < 4; ++k) {
                float rc = c[k] - v[k];
                if (jc0 + k == j1) rc = INF;
                m = fminf(m, rc);
            }
            if (t + 1 < na) LOADROW(c, prow[alist[t + 1]]);

            unsigned mb = __reduce_min_sync(0xffffffffu, __float_as_uint(m));
            if (lane == 0) red1[pp][wrp] = mb;
            __syncthreads();
            const float mu = __uint_as_float(min(min(red1[pp][0], red1[pp][1]),
                                                 min(red1[pp][2], red1[pp][3])));
            if ((unsigned)(j1 - jc0) < 4u) v[j1 - jc0] -= mu;
            if (tid == 0) u[prow[j1]] = mu;
            pp ^= 1;
        }
        __syncthreads();
    }

    int head = 0, tail = s_nfree;
    const int lim = 2 * tail;
    int cnt = 0;

    // ================= augmenting row reduction (bounded JV ARR) ===========
    if (head < tail) LOADROW(c, flist[0]);
    while (head < tail && cnt < lim) {
        const int i = flist[head]; ++head; ++cnt;

        unsigned kk[4];
#pragma unroll
        for (int k = 0; k < 4; ++k) {
            float r0 = c[k] - v[k];
            kk[k] = (__float_as_uint(r0) & ~0x3FFu) | (unsigned)(jc0 + k);
        }
        unsigned m = min(min(kk[0], kk[1]), min(kk[2], kk[3]));
        m = __reduce_min_sync(0xffffffffu, m);
        if (lane == 0) red1[pp][wrp] = m;

        unsigned m2 = 0xFFFFFFFFu;
        __syncthreads();                                            // bar 1
        const unsigned g1 = min(min(red1[pp][0], red1[pp][1]),
                                min(red1[pp][2], red1[pp][3]));
        const int j1 = (int)(g1 & 0x3FFu);

#pragma unroll
        for (int k = 0; k < 4; ++k) m2 = min(m2, (kk[k] == g1) ? 0xFFFFFFFFu : kk[k]);
        m2 = __reduce_min_sync(0xffffffffu, m2);
        if (lane == 0) red2[pp][wrp] = m2;
        __syncthreads();                                            // bar 2
        const unsigned g2 = min(min(red2[pp][0], red2[pp][1]),
                                min(red2[pp][2], red2[pp][3]));
        const int j2 = (int)(g2 & 0x3FFu);
        const float u1 = __uint_as_float(g1 & ~0x3FFu);
        const float u2 = __uint_as_float(g2 & ~0x3FFu);

        int jsel = j1;
        if (u1 < u2) {
            if ((unsigned)(j1 - jc0) < 4u) v[j1 - jc0] -= (u2 - u1);
        } else if (prow[j1] >= 0) {
            jsel = j2;
        }
        if (tid == 0) {
            int iold = prow[jsel];
            prow[jsel] = i;
            u[i] = u2;
            if (iold >= 0) flist[tail] = (short)iold;
            s_iold = iold;
        }
        pp ^= 1;
        __syncthreads();                                            // bar 3
        if (s_iold >= 0) ++tail;
        if (head < tail && cnt < lim) LOADROW(c, flist[head]);
    }

    // ================= shortest augmenting paths ===========================
    if (head < tail) LOADROW(c, flist[head]);

    for (int idx = head; idx < tail; ++idx) {
        const int i = flist[idx];

        float          uinf[4];
        unsigned       key[4];
        unsigned short wreg[4];                  // way[] kept in registers
#pragma unroll
        for (int k = 0; k < 4; ++k) { uinf[k] = 0.f; key[k] = 0xFFFFFFFFu; wreg[k] = ROOTW; }

        float          base = -u[i];
        unsigned short j0s  = ROOTW;
        int   jpred1 = -1, jpred2 = -1;
        int   ipred1 = 0,  ipred2 = 0;
        float upred1 = 0.f, upred2 = 0.f;
        int   jfreeC;
        float dfinal;

        while (true) {
            // ---- relax my 4 columns (way stays in regs: SEL, no STS) ----
#pragma unroll
            for (int k = 0; k < 4; ++k) {
                float cur   = fmaxf((c[k] - v[k]) + base, uinf[k]);
                unsigned pc = (__float_as_uint(cur) & ~0x3FFu)
                              | (unsigned)(jc0 + k);
                if (pc < key[k]) { key[k] = pc; wreg[k] = j0s; }
            }
            unsigned m = min(min(key[0], key[1]), min(key[2], key[3]));
            m = __reduce_min_sync(0xffffffffu, m);
            if (lane == 0) red1[pp][wrp] = m;
            __syncthreads();                              // the ONLY bar per pop
            const uint4 q = *(const uint4*)&red1[pp][0];  // one LDS.128
            const unsigned gmin = min(min(q.x, q.y), min(q.z, q.w));
            const int   j1 = (int)(gmin & 0x3FFu);
            const float dl = __uint_as_float(gmin & ~0x3FFu);

            int   i1;
            float ui1;
            // ---- hit path: row, dual, and data all in registers ----
            if (j1 == jpred1) {
                i1 = ipred1; ui1 = upred1;
#pragma unroll
                for (int k = 0; k < 4; ++k) c[k] = cS[k];
            } else if (j1 == jpred2) {
                i1 = ipred2; ui1 = upred2;
#pragma unroll
                for (int k = 0; k < 4; ++k) c[k] = cT[k];
            } else {
                i1 = prow[j1];                            // miss: LDS
                if (i1 < 0) {
                    // owner publishes way for the free column before the
                    // post-loop barrier (orders it before tid0's augment walk)
#pragma unroll
                    for (int k = 0; k < 4; ++k)
                        if (key[k] == gmin) way[jc0 + k] = wreg[k];
                    jfreeC = j1; dfinal = dl; pp ^= 1; break;
                }
                LOADROW(c, i1);                           // LDG first ...
                ui1 = u[i1];                              // ... u LDS overlaps it
            }

            // ---- owner poisons its popped column; publishes dpop + way ----
#pragma unroll
            for (int k = 0; k < 4; ++k)
                if (key[k] == gmin) {
                    uinf[k] = INF;
                    key[k]  = 0x7F800000u | (unsigned)(jc0 + k);
                    dpop[jc0 + k] = dl;
                    way[jc0 + k]  = wreg[k];
                }

            // ---- predictions: 2 smallest losing warp minima, batched issue -
            {
                unsigned cA = 0xFFFFFFFFu, cB = 0xFFFFFFFFu, x;
                x = q.x; if (x != gmin) { if (x < cA) { cB = cA; cA = x; } else cB = min(cB, x); }
                x = q.y; if (x != gmin) { if (x < cA) { cB = cA; cA = x; } else cB = min(cB, x); }
                x = q.z; if (x != gmin) { if (x < cA) { cB = cA; cA = x; } else cB = min(cB, x); }
                x = q.w; if (x != gmin) { if (x < cA) { cB = cA; cA = x; } else cB = min(cB, x); }
                const int jpA = (int)(cA & 0x3FFu);
                const int jpB = (int)(cB & 0x3FFu);
                const bool okA = (cA < 0x7F800000u);
                const bool okB = (cB < 0x7F800000u) && (jpB != jpA);
                const int ipA = okA ? prow[jpA] : -1;
                const int ipB = okB ? prow[jpB] : -1;
                jpred1 = jpred2 = -1;
                if (ipA >= 0) LOADROW(cS, ipA);
                if (ipB >= 0) LOADROW(cT, ipB);
                if (ipA >= 0) { jpred1 = jpA; ipred1 = ipA; upred1 = u[ipA]; }
                if (ipB >= 0) { jpred2 = jpB; ipred2 = ipB; upred2 = u[ipB]; }
            }

            base = dl - ui1;
            j0s  = (unsigned short)j1;
            pp  ^= 1;
        }

        __syncthreads();              // dpop/way visible; all past break

        // prefetch next root row before serial tail
        if (idx + 1 < tail) LOADROW(c, flist[idx + 1]);

        // ---- one-shot dual updates ----
#pragma unroll
        for (int k = 0; k < 4; ++k) {
            if (uinf[k] > 0.f) {                  // col was popped
                int   j   = jc0 + k;
                float adj = dfinal - dpop[j];
                v[k]       -= adj;
                u[prow[j]] += adj;                // distinct rows: race-free
            }
        }
        if (tid == 0) u[i] += dfinal;
        __syncthreads();

        // ---- augment along alternating path (serial, tid 0) ----
        if (tid == 0) {
            int j = jfreeC;
            while (true) {
                int jpth = way[j];
                if (jpth == ROOTW) { prow[j] = i; break; }
                prow[j] = prow[jpth];
                j = jpth;
            }
        }
        __syncthreads();
    }

    // ---- matched-cost sum (double, deterministic order) ----
    double s = 0.0;
#pragma unroll
    for (int k = 0; k < 4; ++k) {
        int j = jc0 + k;
        s += (double)__ldg(&C[(size_t)prow[j] * N + j]);
    }
#pragma unroll
    for (int off = 16; off; off >>= 1)
        s += __shfl_down_sync(0xffffffffu, s, off);
    if (lane == 0) red_s[wrp] = s;
    __syncthreads();
    if (tid == 0)
        g_batch_sums[b] = ((red_s[0] + red_s[1]) + (red_s[2] + red_s[3]));
}

__global__ void finalize_kernel(float* __restrict__ out)
{
    const int lane = threadIdx.x;
    double s = (lane < B) ? g_batch_sums[lane] : 0.0;
#pragma unroll
    for (int off = 16; off; off >>= 1)
        s += __shfl_down_sync(0xffffffffu, s, off);
    if (lane == 0) out[0] = (float)(s / (double)(B * N));
}

extern "C" void kernel_launch(void* const* d_in, const int* in_sizes, int n_in,
                              void* d_out, int out_size)
{
    const float* D = (const float*)d_in[0];
    lap_kernel<<<B, NT>>>(D);
    finalize_kernel<<<1, 32>>>((float*)d_out);
}